// round 1
// baseline (speedup 1.0000x reference)
#include <cuda_runtime.h>

#define Nn 768
#define Hh 32
#define Ee 24576
#define Pp 4096
#define NCH 8
#define CW 96

// ---------------- scratch (__device__ globals: allocation-free) ----------------
__device__ unsigned char d_adj[Nn*Nn];          // dedup adjacency (0/1)
__device__ float d_dinv[Nn];
__device__ float d_h [Nn*Hh];                   // current node features
__device__ float d_hT[Nn*Hh];                   // dinv[j] * (h @ W)
__device__ float d_hP[Nn*Hh];                   // pre-norm GCN output
__device__ int   d_cnt2[Nn*NCH];                // per-(row,chunk) edge counts
__device__ int   d_base[Nn*NCH+1];              // scanned chunk pointers
__device__ int   d_fill[Nn*NCH];                // fill cursors
__device__ int   d_col [Ee];                    // CSR (chunk-bucketed) dst
__device__ int   d_eid [Ee];                    // CSR slot -> original edge id
__device__ float d_xe [Ee*Hh];                  // edge MLP1 output, CSR order
__device__ float d_mul[Ee*Hh];                  // edge MLP2 output, CSR order
__device__ float d_z  [(size_t)Nn*Nn*Hh];       // raw z (pre-norm), masked entries only
__device__ unsigned char d_maskb[Nn*Nn];        // (af@af>0)|adj
__device__ float d_S1[Hh];
__device__ float d_S2[Hh];
__device__ int   d_cntM;
__device__ float d_meanv[Hh];
__device__ float d_istd [Hh];

// ---------------- kernels ----------------
__global__ void k_init() {
    int idx = blockIdx.x*blockDim.x + threadIdx.x;
    int* adjI = (int*)d_adj;
    if (idx < Nn*Nn/4) adjI[idx] = 0;
    if (idx < Nn*NCH) d_cnt2[idx] = 0;
    if (idx < Hh) { d_S1[idx] = 0.f; d_S2[idx] = 0.f; }
    if (idx == 0) d_cntM = 0;
}

__global__ void k_scatter(const int* __restrict__ ei) {
    int e = blockIdx.x*blockDim.x + threadIdx.x;
    if (e >= Ee) return;
    int u = ei[e], v = ei[Ee+e];
    d_adj[u*Nn+v] = 1;
    atomicAdd(&d_cnt2[u*NCH + v/CW], 1);
}

__global__ void k_embed(const int* __restrict__ x, const float* __restrict__ emb) {
    int idx = blockIdx.x*blockDim.x + threadIdx.x;
    if (idx >= Nn*Hh) return;
    d_h[idx] = emb[x[idx>>5]*Hh + (idx & 31)];
}

__global__ void k_dinv() {
    int w = threadIdx.x>>5, lane = threadIdx.x&31;
    int i = blockIdx.x*8 + w;
    int s = 0;
    #pragma unroll
    for (int t=0;t<Nn/32;t++) s += d_adj[i*Nn + t*32 + lane];
    for (int o=16;o;o>>=1) s += __shfl_down_sync(0xffffffffu, s, o);
    if (lane==0) d_dinv[i] = rsqrtf((float)s + 1.0f);   // Ahat row sum = adj row sum + 1
}

__global__ void k_scan() {
    __shared__ int tot[257];
    int tid = threadIdx.x;
    int lo = tid*24;
    int vals[24];
    int run = 0;
    #pragma unroll
    for (int q=0;q<24;q++){ vals[q]=run; run += d_cnt2[lo+q]; }
    tot[tid] = run;
    __syncthreads();
    if (tid==0){ int r=0; for (int t=0;t<256;t++){ int xx=tot[t]; tot[t]=r; r+=xx; } tot[256]=r; }
    __syncthreads();
    int base = tot[tid];
    #pragma unroll
    for (int q=0;q<24;q++){ int v = base + vals[q]; d_base[lo+q]=v; d_fill[lo+q]=v; }
    if (tid==0) d_base[Nn*NCH] = tot[256];
}

__global__ void k_fill(const int* __restrict__ ei) {
    int e = blockIdx.x*blockDim.x + threadIdx.x;
    if (e >= Ee) return;
    int u = ei[e], v = ei[Ee+e];
    int s = atomicAdd(&d_fill[u*NCH + v/CW], 1);
    d_col[s] = v;
    d_eid[s] = e;
}

__global__ void k_hW(const float* __restrict__ gcnW, int l) {
    int w = threadIdx.x>>5, lane = threadIdx.x&31;
    int i = blockIdx.x*8 + w;
    const float* W = gcnW + l*Hh*Hh;
    float hv = d_h[i*Hh+lane];
    float acc = 0.f;
    #pragma unroll
    for (int k=0;k<32;k++) acc += __shfl_sync(0xffffffffu,hv,k) * W[k*Hh+lane];
    d_hT[i*Hh+lane] = d_dinv[i]*acc;
}

__global__ void k_agg(const float* __restrict__ gcnb, int l) {
    int w = threadIdx.x>>5, lane = threadIdx.x&31;
    int i = blockIdx.x*8 + w;
    const unsigned char* row = d_adj + i*Nn;
    float acc = 0.f;
    for (int jb=0;jb<Nn;jb+=32) {
        unsigned m = __ballot_sync(0xffffffffu, row[jb+lane]!=0);
        while (m) { int b = __ffs(m)-1; m &= m-1; acc += d_hT[(jb+b)*Hh+lane]; }
    }
    // Ahat = A + I  =>  extra dinv[i]*hW[i] term (= d_hT[i])
    d_hP[i*Hh+lane] = d_dinv[i]*(acc + d_hT[i*Hh+lane]) + gcnb[l*Hh+lane];
}

__global__ void k_norm() {
    __shared__ float sS[32][32], sQ[32][32], sM[32], sI[32];
    int w = threadIdx.x>>5, lane = threadIdx.x&31;
    float s=0.f, q=0.f;
    for (int r=w;r<Nn;r+=32){ float v=d_hP[r*Hh+lane]; s+=v; q+=v*v; }
    sS[w][lane]=s; sQ[w][lane]=q;
    __syncthreads();
    if (w==0){
        float ts=0.f, tq=0.f;
        #pragma unroll
        for (int r=0;r<32;r++){ ts+=sS[r][lane]; tq+=sQ[r][lane]; }
        float mean = ts/(float)Nn;
        float var  = tq/(float)Nn - mean*mean;   // E[(v-mean)^2]
        sM[lane]=mean; sI[lane]=rsqrtf(var+1e-5f);
    }
    __syncthreads();
    float mean=sM[lane], inv=sI[lane];
    for (int r=w;r<Nn;r+=32){
        float v=d_hP[r*Hh+lane];
        d_h[r*Hh+lane]=fmaxf((v-mean)*inv,0.f);
    }
}

__global__ void k_mlp(const int* __restrict__ ei,
                      const float* __restrict__ W1, const float* __restrict__ b1,
                      const float* __restrict__ W2, const float* __restrict__ b2) {
    int w = threadIdx.x>>5, lane = threadIdx.x&31;
    int s = blockIdx.x*8 + w;
    int e = d_eid[s];
    int u = ei[e], v = ei[Ee+e];
    float hu = d_h[u*Hh+lane], hv = d_h[v*Hh+lane];
    float x1 = b1[lane], x2 = b2[lane];
    #pragma unroll
    for (int k=0;k<32;k++){
        float a = __shfl_sync(0xffffffffu,hu,k);
        float b = __shfl_sync(0xffffffffu,hv,k);
        x1 += a*W1[k*Hh+lane] + b*W1[(k+32)*Hh+lane];
        x2 += a*W2[k*Hh+lane] + b*W2[(k+32)*Hh+lane];
    }
    d_xe [s*Hh+lane]=fmaxf(x1,0.f);
    d_mul[s*Hh+lane]=fmaxf(x2,0.f);
}

// The hot kernel: per-row sparse 2-hop accumulation (C row in smem) + z GEMM +
// masked moments + masked z store. Warp w owns j in [96w, 96w+96) -> no smem atomics.
__global__ void __launch_bounds__(256,2) k_rowC(const float* __restrict__ W3,
                                                const float* __restrict__ b3v) {
    extern __shared__ float Cs[];                         // Nn*Hh floats
    unsigned char* touched = (unsigned char*)(Cs + Nn*Hh); // Nn bytes
    int tid = threadIdx.x, w = tid>>5, lane = tid&31;
    int i = blockIdx.x;

    float4 z4 = make_float4(0.f,0.f,0.f,0.f);
    for (int t=tid; t<Nn*Hh/4; t+=256) ((float4*)Cs)[t]=z4;
    for (int t=tid; t<Nn; t+=256) touched[t]=0;
    __syncthreads();

    // phase 2: for each e=(i,k), each warp scans CSR[k]'s slice in its own j-chunk
    int es = d_base[i*NCH], ee = d_base[(i+1)*NCH];
    for (int e=es; e<ee; e++){
        int k = d_col[e];
        float xv = d_xe[e*Hh+lane];
        int fs = d_base[k*NCH+w], fe = d_base[k*NCH+w+1];
        for (int f=fs; f<fe; f++){
            int j = d_col[f];
            Cs[j*Hh+lane] += xv * d_mul[f*Hh+lane];
            if (lane==0) touched[j]=1;
        }
    }
    __syncthreads();

    // phase 3: z = C @ W3[:32] + af*W3[32] + b3 ; masked moments + store
    float w3[33];
    #pragma unroll
    for (int k=0;k<33;k++) w3[k]=W3[k*Hh+lane];
    float bb = b3v[lane];
    float s1=0.f, s2=0.f; int c0=0;
    for (int j=w; j<Nn; j+=8){
        unsigned char af = d_adj[i*Nn+j];
        unsigned char tc = touched[j];
        unsigned char m = (unsigned char)(af | tc);
        if (lane==0) d_maskb[i*Nn+j]=m;
        if (!m) continue;                         // warp-uniform
        float acc = bb + (af ? w3[32] : 0.f);
        const float4* Cj = (const float4*)(Cs + j*Hh);
        #pragma unroll
        for (int k4=0;k4<8;k4++){
            float4 c = Cj[k4];
            acc += c.x*w3[4*k4] + c.y*w3[4*k4+1] + c.z*w3[4*k4+2] + c.w*w3[4*k4+3];
        }
        d_z[((size_t)i*Nn+j)*Hh+lane] = acc;
        s1 += acc; s2 += acc*acc; c0++;
    }
    atomicAdd(&d_S1[lane], s1);
    atomicAdd(&d_S2[lane], s2);
    if (lane==0) atomicAdd(&d_cntM, c0);
}

__global__ void k_stats() {
    int t = threadIdx.x;
    if (t < Hh) {
        float c = (float)d_cntM;
        float mean = d_S1[t]/c;
        d_meanv[t]=mean;
        d_istd[t]=rsqrtf(d_S2[t]/c - mean*mean + 1e-5f);
    }
}

__global__ void k_pos(const int* __restrict__ pos, const float* __restrict__ linW,
                      const float* __restrict__ linb, float* __restrict__ out) {
    int w = threadIdx.x>>5, lane = threadIdx.x&31;
    int p = blockIdx.x*8 + w;
    int p0 = pos[2*p], p1 = pos[2*p+1];
    float acc = d_h[p0*Hh+lane]*d_h[p1*Hh+lane]*linW[Hh+lane];   // xx term
    if (d_maskb[p0*Nn+p1]) {                                     // mask is symmetric
        float mean = d_meanv[lane], inv = d_istd[lane];
        float zq1 = d_z[((size_t)p0*Nn+p1)*Hh+lane];
        float zq2 = d_z[((size_t)p1*Nn+p0)*Hh+lane];
        float r1 = fmaxf((zq1-mean)*inv,0.f);
        float r2 = fmaxf((zq2-mean)*inv,0.f);
        acc += r1*r2*linW[lane];
    }
    for (int o=16;o;o>>=1) acc += __shfl_down_sync(0xffffffffu,acc,o);
    if (lane==0) out[p] = acc + linb[0];
}

// ---------------- launch ----------------
extern "C" void kernel_launch(void* const* d_in, const int* in_sizes, int n_in,
                              void* d_out, int out_size) {
    const int*   x    = (const int*)  d_in[0];
    const int*   ei   = (const int*)  d_in[1];
    const int*   pos  = (const int*)  d_in[2];
    const float* emb  = (const float*)d_in[3];
    const float* gcnW = (const float*)d_in[4];
    const float* gcnb = (const float*)d_in[5];
    const float* W1   = (const float*)d_in[6];
    const float* b1   = (const float*)d_in[7];
    const float* W2   = (const float*)d_in[8];
    const float* b2   = (const float*)d_in[9];
    const float* W3   = (const float*)d_in[10];
    const float* b3   = (const float*)d_in[11];
    const float* linW = (const float*)d_in[12];
    const float* linb = (const float*)d_in[13];
    float* out = (float*)d_out;

    const int smemC = Nn*Hh*(int)sizeof(float) + Nn + 256;   // ~99.3 KB
    cudaFuncSetAttribute(k_rowC, cudaFuncAttributeMaxDynamicSharedMemorySize, smemC);

    k_init   <<<576,256>>>();
    k_scatter<<<96, 256>>>(ei);
    k_embed  <<<96, 256>>>(x, emb);
    k_dinv   <<<96, 256>>>();
    k_scan   <<<1,  256>>>();
    k_fill   <<<96, 256>>>(ei);
    for (int l=0;l<2;l++){
        k_hW  <<<96,256>>>(gcnW, l);
        k_agg <<<96,256>>>(gcnb, l);
        k_norm<<<1,1024>>>();
    }
    k_mlp <<<3072,256>>>(ei, W1,b1,W2,b2);
    k_rowC<<<768,256,smemC>>>(W3,b3);
    k_stats<<<1,32>>>();
    k_pos <<<512,256>>>(pos, linW, linb, out);
}